// round 5
// baseline (speedup 1.0000x reference)
#include <cuda_runtime.h>
#include <cuda_bf16.h>
#include <cstdint>
#include <math.h>

#define Bq 4
#define Sq 2048
#define DMq 512
#define Hq 8
#define BSq (Bq * Sq)
#define Y_ELEMS ((size_t)Bq * Sq * DMq)
#define NROWS (Bq * Hq * Sq)
#define NTILES 16

// Scratch (__device__ globals; no allocation allowed)
__device__ __nv_bfloat16 g_qhi[Bq * Sq * DMq];
__device__ __nv_bfloat16 g_qlo[Bq * Sq * DMq];
__device__ __nv_bfloat16 g_khi[Bq * Sq * DMq];
__device__ __nv_bfloat16 g_klo[Bq * Sq * DMq];
__device__ __nv_bfloat16 g_vhi[Bq * Sq * DMq];
__device__ __nv_bfloat16 g_vlo[Bq * Sq * DMq];
__device__ float g_ctx[Bq * Sq * DMq];
__device__ float g_pm[(size_t)NROWS * NTILES];
__device__ float g_pz[(size_t)NROWS * NTILES];
__device__ float g_rowm[NROWS];
__device__ float g_rowinv[NROWS];

// ---------------------------------------------------------------------------
__device__ __forceinline__ uint32_t smem_u32(const void* p) {
    uint32_t a;
    asm("{ .reg .u64 t; cvta.to.shared.u64 t, %1; cvt.u32.u64 %0, t; }"
        : "=r"(a) : "l"(p));
    return a;
}

__device__ __forceinline__ void ldsm_x4(uint32_t* r, uint32_t addr) {
    asm volatile("ldmatrix.sync.aligned.m8n8.x4.shared.b16 {%0,%1,%2,%3}, [%4];"
                 : "=r"(r[0]), "=r"(r[1]), "=r"(r[2]), "=r"(r[3]) : "r"(addr));
}

__device__ __forceinline__ void ldsm_x4_trans(uint32_t* r, uint32_t addr) {
    asm volatile("ldmatrix.sync.aligned.m8n8.x4.trans.shared.b16 {%0,%1,%2,%3}, [%4];"
                 : "=r"(r[0]), "=r"(r[1]), "=r"(r[2]), "=r"(r[3]) : "r"(addr));
}

__device__ __forceinline__ void mma_bf16(float* d, const uint32_t* a,
                                         uint32_t b0, uint32_t b1) {
    asm volatile(
        "mma.sync.aligned.m16n8k16.row.col.f32.bf16.bf16.f32 "
        "{%0,%1,%2,%3}, {%4,%5,%6,%7}, {%8,%9}, {%0,%1,%2,%3};"
        : "+f"(d[0]), "+f"(d[1]), "+f"(d[2]), "+f"(d[3])
        : "r"(a[0]), "r"(a[1]), "r"(a[2]), "r"(a[3]), "r"(b0), "r"(b1));
}

__device__ __forceinline__ uint32_t pack_bf16(float x, float y) {
    __nv_bfloat162 t = __floats2bfloat162_rn(x, y);
    return *reinterpret_cast<uint32_t*>(&t);
}

// hi/lo split of a float pair into two packed bf16x2 registers
__device__ __forceinline__ void hilo2(float x, float y, uint32_t& hi, uint32_t& lo) {
    __nv_bfloat16 hx = __float2bfloat16_rn(x), hy = __float2bfloat16_rn(y);
    __nv_bfloat162 hv;
    hv.x = hx; hv.y = hy;
    hi = *reinterpret_cast<uint32_t*>(&hv);
    lo = pack_bf16(x - __bfloat162float(hx), y - __bfloat162float(hy));
}

// ---------------------------------------------------------------------------
// Projection GEMM + bias, 128x128 tile, BK=16, 256 threads, 8x8/thread.
// ---------------------------------------------------------------------------
__global__ __launch_bounds__(256) void gemm_bias128_kernel(
    const float* __restrict__ A, const float* __restrict__ W,
    const float* __restrict__ bias, float* __restrict__ Cf,
    __nv_bfloat16* __restrict__ Chi, __nv_bfloat16* __restrict__ Clo,
    int M, int N, int K)
{
    __shared__ float As[16][132];
    __shared__ float Ws[16][132];
    int tid = threadIdx.x;
    int ty = tid >> 4, tx = tid & 15;
    int m0 = blockIdx.y * 128, n0 = blockIdx.x * 128;

    float acc[8][8] = {};
    int lrow = tid >> 1;
    int lseg = (tid & 1) * 8;
    int wrow = tid >> 4;
    int wcol = (tid & 15) * 8;

    for (int k0 = 0; k0 < K; k0 += 16) {
        float4 a0 = *(const float4*)&A[(size_t)(m0 + lrow) * K + k0 + lseg];
        float4 a1 = *(const float4*)&A[(size_t)(m0 + lrow) * K + k0 + lseg + 4];
        As[lseg + 0][lrow] = a0.x; As[lseg + 1][lrow] = a0.y;
        As[lseg + 2][lrow] = a0.z; As[lseg + 3][lrow] = a0.w;
        As[lseg + 4][lrow] = a1.x; As[lseg + 5][lrow] = a1.y;
        As[lseg + 6][lrow] = a1.z; As[lseg + 7][lrow] = a1.w;
        float4 w0 = *(const float4*)&W[(size_t)(k0 + wrow) * N + n0 + wcol];
        float4 w1 = *(const float4*)&W[(size_t)(k0 + wrow) * N + n0 + wcol + 4];
        *(float4*)&Ws[wrow][wcol] = w0;
        *(float4*)&Ws[wrow][wcol + 4] = w1;
        __syncthreads();
#pragma unroll
        for (int kk = 0; kk < 16; kk++) {
            float4 af0 = *(float4*)&As[kk][ty * 8];
            float4 af1 = *(float4*)&As[kk][ty * 8 + 4];
            float4 bf0 = *(float4*)&Ws[kk][tx * 8];
            float4 bf1 = *(float4*)&Ws[kk][tx * 8 + 4];
            float a[8] = {af0.x, af0.y, af0.z, af0.w, af1.x, af1.y, af1.z, af1.w};
            float bb[8] = {bf0.x, bf0.y, bf0.z, bf0.w, bf1.x, bf1.y, bf1.z, bf1.w};
#pragma unroll
            for (int i = 0; i < 8; i++)
#pragma unroll
                for (int j = 0; j < 8; j++)
                    acc[i][j] = fmaf(a[i], bb[j], acc[i][j]);
        }
        __syncthreads();
    }

    float bv[8];
#pragma unroll
    for (int j = 0; j < 8; j++) bv[j] = bias[n0 + tx * 8 + j];

#pragma unroll
    for (int i = 0; i < 8; i++) {
        size_t row = (size_t)(m0 + ty * 8 + i);
#pragma unroll
        for (int j = 0; j < 8; j++) {
            size_t idx = row * N + n0 + tx * 8 + j;
            float val = acc[i][j] + bv[j];
            if (Cf) Cf[idx] = val;
            if (Chi) {
                __nv_bfloat16 hb = __float2bfloat16_rn(val);
                float rem = val - __bfloat162float(hb);
                Chi[idx] = hb;
                Clo[idx] = __float2bfloat16_rn(rem);
            }
        }
    }
}

// ---------------------------------------------------------------------------
// Stats kernel: scores via mma.sync bf16x3; NO att store; writes per-tile
// softmax partials (row max, row expsum).
// ---------------------------------------------------------------------------
#define SC_TILE_BYTES (128 * 144)
#define SC_STATS_OFF (4 * SC_TILE_BYTES)
#define SC_SMEM_BYTES (4 * SC_TILE_BYTES + 2048)

__global__ __launch_bounds__(256, 2) void stats_mma_kernel(
    const __nv_bfloat16* __restrict__ qhi, const __nv_bfloat16* __restrict__ qlo,
    const __nv_bfloat16* __restrict__ khi, const __nv_bfloat16* __restrict__ klo,
    const float* __restrict__ mask,
    float* __restrict__ pm, float* __restrict__ pz)
{
    extern __shared__ char sm[];
    char* bp = sm;
    uint32_t sb = smem_u32(sm);
    const uint32_t QHIo = 0, QLOo = SC_TILE_BYTES, KHIo = 2 * SC_TILE_BYTES,
                   KLOo = 3 * SC_TILE_BYTES;
    float* sm_m = (float*)(bp + SC_STATS_OFF);
    float* sm_z = sm_m + 256;

    int tid = threadIdx.x;
    int lane = tid & 31, wid = tid >> 5;
    int wq = wid >> 1, wn = wid & 1;
    int bh = blockIdx.z, b = bh >> 3, h = bh & 7;
    int q0 = blockIdx.y * 128;
    int n0 = blockIdx.x * 128;

    for (int it = tid; it < 1024; it += 256) {
        int row = it >> 3, ch = it & 7;
        int so = row * 144 + ch * 16;
        size_t gq = ((size_t)(b * Sq + q0 + row)) * DMq + h * 64 + ch * 8;
        size_t gk = ((size_t)(b * Sq + n0 + row)) * DMq + h * 64 + ch * 8;
        *(uint4*)(bp + QHIo + so) = *(const uint4*)(qhi + gq);
        *(uint4*)(bp + QLOo + so) = *(const uint4*)(qlo + gq);
        *(uint4*)(bp + KHIo + so) = *(const uint4*)(khi + gk);
        *(uint4*)(bp + KLOo + so) = *(const uint4*)(klo + gk);
    }
    __syncthreads();

    float acc[2][8][4] = {};

    const uint32_t Aoff[3] = {QHIo, QHIo, QLOo};
    const uint32_t Boff[3] = {KHIo, KLOo, KHIo};

#pragma unroll
    for (int p = 0; p < 3; p++) {
        uint32_t abase = sb + Aoff[p] + (wq * 32) * 144;
        uint32_t bbase = sb + Boff[p] + (wn * 64) * 144;
        uint32_t arow = lane & 15;
        uint32_t acolb = (lane >> 4) * 16;
#pragma unroll
        for (int kt = 0; kt < 4; kt++) {
            uint32_t a0[4], a1[4];
            ldsm_x4(a0, abase + arow * 144 + acolb + kt * 32);
            ldsm_x4(a1, abase + (16 + arow) * 144 + acolb + kt * 32);
            uint32_t brow = (lane & 7) + ((lane & 16) ? 8 : 0);
            uint32_t bcolb = ((lane >> 3) & 1) * 16 + kt * 32;
#pragma unroll
            for (int np = 0; np < 4; np++) {
                uint32_t bb[4];
                ldsm_x4(bb, bbase + (brow + np * 16) * 144 + bcolb);
                mma_bf16(acc[0][np * 2 + 0], a0, bb[0], bb[1]);
                mma_bf16(acc[0][np * 2 + 1], a0, bb[2], bb[3]);
                mma_bf16(acc[1][np * 2 + 0], a1, bb[0], bb[1]);
                mma_bf16(acc[1][np * 2 + 1], a1, bb[2], bb[3]);
            }
        }
    }

    int g = lane >> 2, tg = lane & 3;
    float mrow[4] = {-1e30f, -1e30f, -1e30f, -1e30f};
#pragma unroll
    for (int ni = 0; ni < 8; ni++) {
        int col = n0 + wn * 64 + ni * 8 + tg * 2;
        float2 mv = *(const float2*)&mask[(size_t)b * Sq + col];
        float mx = mv.x * -1e9f, my = mv.y * -1e9f;
#pragma unroll
        for (int mi = 0; mi < 2; mi++) {
            float v0 = acc[mi][ni][0] * 0.125f + mx;
            float v1 = acc[mi][ni][1] * 0.125f + my;
            float v2 = acc[mi][ni][2] * 0.125f + mx;
            float v3 = acc[mi][ni][3] * 0.125f + my;
            mrow[mi * 2 + 0] = fmaxf(mrow[mi * 2 + 0], fmaxf(v0, v1));
            mrow[mi * 2 + 1] = fmaxf(mrow[mi * 2 + 1], fmaxf(v2, v3));
        }
    }
#pragma unroll
    for (int r = 0; r < 4; r++) {
        mrow[r] = fmaxf(mrow[r], __shfl_xor_sync(0xffffffffu, mrow[r], 1));
        mrow[r] = fmaxf(mrow[r], __shfl_xor_sync(0xffffffffu, mrow[r], 2));
    }
    float zrow[4] = {0.f, 0.f, 0.f, 0.f};
#pragma unroll
    for (int ni = 0; ni < 8; ni++) {
        int col = n0 + wn * 64 + ni * 8 + tg * 2;
        float2 mv = *(const float2*)&mask[(size_t)b * Sq + col];
        float mx = mv.x * -1e9f, my = mv.y * -1e9f;
#pragma unroll
        for (int mi = 0; mi < 2; mi++) {
            float v0 = acc[mi][ni][0] * 0.125f + mx;
            float v1 = acc[mi][ni][1] * 0.125f + my;
            float v2 = acc[mi][ni][2] * 0.125f + mx;
            float v3 = acc[mi][ni][3] * 0.125f + my;
            zrow[mi * 2 + 0] += __expf(v0 - mrow[mi * 2 + 0]) + __expf(v1 - mrow[mi * 2 + 0]);
            zrow[mi * 2 + 1] += __expf(v2 - mrow[mi * 2 + 1]) + __expf(v3 - mrow[mi * 2 + 1]);
        }
    }
#pragma unroll
    for (int r = 0; r < 4; r++) {
        zrow[r] += __shfl_xor_sync(0xffffffffu, zrow[r], 1);
        zrow[r] += __shfl_xor_sync(0xffffffffu, zrow[r], 2);
    }
    if (tg == 0) {
#pragma unroll
        for (int mi = 0; mi < 2; mi++) {
#pragma unroll
            for (int half = 0; half < 2; half++) {
                int rloc = wq * 32 + mi * 16 + g + half * 8;
                sm_m[wn * 128 + rloc] = mrow[mi * 2 + half];
                sm_z[wn * 128 + rloc] = zrow[mi * 2 + half];
            }
        }
    }
    __syncthreads();
    if (tid < 128) {
        float m0 = sm_m[tid], m1 = sm_m[128 + tid];
        float mm = fmaxf(m0, m1);
        float zz = sm_z[tid] * __expf(m0 - mm) + sm_z[128 + tid] * __expf(m1 - mm);
        size_t pidx = ((size_t)bh * Sq + q0 + tid) * NTILES + blockIdx.x;
        pm[pidx] = mm;
        pz[pidx] = zz;
    }
}

// ---------------------------------------------------------------------------
__global__ __launch_bounds__(256) void softmax_reduce_kernel(
    const float* __restrict__ pm, const float* __restrict__ pz,
    float* __restrict__ rowm, float* __restrict__ rowinv)
{
    int idx = blockIdx.x * 256 + threadIdx.x;
    if (idx >= NROWS) return;
    const float* pmp = pm + (size_t)idx * NTILES;
    const float* pzp = pz + (size_t)idx * NTILES;
    float m = -1e30f;
#pragma unroll
    for (int t = 0; t < NTILES; t++) m = fmaxf(m, pmp[t]);
    float z = 0.f;
#pragma unroll
    for (int t = 0; t < NTILES; t++) z += pzp[t] * __expf(pmp[t] - m);
    rowm[idx] = m;
    rowinv[idx] = 1.0f / z;
}

// ---------------------------------------------------------------------------
// Fused attention: recompute S = QK^T (bf16x3), p = exp(s-m)*invZ,
// write normalized att once, ctx += p @ V (bf16x3, p from registers).
// Per CTA: (bh, 128 q rows); loop over 64-key chunks.
// ---------------------------------------------------------------------------
#define FA_QHIo 0
#define FA_QLOo 18432
#define FA_KHIo 36864
#define FA_KLOo 46080
#define FA_VHIo 55296
#define FA_VLOo 64512
#define FA_STATo 73728
#define FA_SMEM_BYTES (73728 + 1024)

__global__ __launch_bounds__(256) void attn_fused_kernel(
    const __nv_bfloat16* __restrict__ qhi, const __nv_bfloat16* __restrict__ qlo,
    const __nv_bfloat16* __restrict__ khi, const __nv_bfloat16* __restrict__ klo,
    const __nv_bfloat16* __restrict__ vhi, const __nv_bfloat16* __restrict__ vlo,
    const float* __restrict__ mask,
    const float* __restrict__ rowm, const float* __restrict__ rowinv,
    float* __restrict__ att, float* __restrict__ ctx)
{
    extern __shared__ char sm[];
    char* bp = sm;
    uint32_t sb = smem_u32(sm);
    float* sm_m = (float*)(bp + FA_STATo);
    float* sm_iz = sm_m + 128;

    int tid = threadIdx.x;
    int lane = tid & 31, wid = tid >> 5;
    int g = lane >> 2, tg = lane & 3;
    int bh = blockIdx.y, b = bh >> 3, h = bh & 7;
    int q0 = blockIdx.x * 128;

    // Q tile (resident) + row stats
    for (int it = tid; it < 1024; it += 256) {
        int row = it >> 3, ch = it & 7;
        int so = row * 144 + ch * 16;
        size_t gq = ((size_t)(b * Sq + q0 + row)) * DMq + h * 64 + ch * 8;
        *(uint4*)(bp + FA_QHIo + so) = *(const uint4*)(qhi + gq);
        *(uint4*)(bp + FA_QLOo + so) = *(const uint4*)(qlo + gq);
    }
    if (tid < 128) {
        sm_m[tid] = rowm[(size_t)bh * Sq + q0 + tid];
        sm_iz[tid] = rowinv[(size_t)bh * Sq + q0 + tid];
    }
    __syncthreads();

    float mr0 = sm_m[wid * 16 + g], iz0 = sm_iz[wid * 16 + g];
    float mr1 = sm_m[wid * 16 + g + 8], iz1 = sm_iz[wid * 16 + g + 8];

    float cacc[8][4] = {};

    const uint32_t Ao[3] = {FA_QHIo, FA_QHIo, FA_QLOo};
    const uint32_t Bo[3] = {FA_KHIo, FA_KLOo, FA_KHIo};

    for (int k0 = 0; k0 < Sq; k0 += 64) {
        // Load K/V chunk (64 rows x 64 cols, hi/lo)
        for (int it = tid; it < 512; it += 256) {
            int row = it >> 3, ch = it & 7;
            int so = row * 144 + ch * 16;
            size_t gk = ((size_t)(b * Sq + k0 + row)) * DMq + h * 64 + ch * 8;
            *(uint4*)(bp + FA_KHIo + so) = *(const uint4*)(khi + gk);
            *(uint4*)(bp + FA_KLOo + so) = *(const uint4*)(klo + gk);
            *(uint4*)(bp + FA_VHIo + so) = *(const uint4*)(vhi + gk);
            *(uint4*)(bp + FA_VLOo + so) = *(const uint4*)(vlo + gk);
        }
        __syncthreads();

        // Scores: warp tile 16 rows x 64 cols
        float sacc[8][4] = {};
#pragma unroll
        for (int p = 0; p < 3; p++) {
            uint32_t abase = sb + Ao[p] + (wid * 16) * 144;
            uint32_t bbase = sb + Bo[p];
            uint32_t arow = lane & 15;
            uint32_t acolb = (lane >> 4) * 16;
            uint32_t brow = (lane & 7) + ((lane & 16) ? 8 : 0);
            uint32_t bcolb = ((lane >> 3) & 1) * 16;
#pragma unroll
            for (int kt = 0; kt < 4; kt++) {
                uint32_t a0[4];
                ldsm_x4(a0, abase + arow * 144 + acolb + kt * 32);
#pragma unroll
                for (int np = 0; np < 4; np++) {
                    uint32_t bb[4];
                    ldsm_x4(bb, bbase + (brow + np * 16) * 144 + bcolb + kt * 32);
                    mma_bf16(sacc[np * 2 + 0], a0, bb[0], bb[1]);
                    mma_bf16(sacc[np * 2 + 1], a0, bb[2], bb[3]);
                }
            }
        }

        // p = exp(scale*s + mask - m) * invZ; store att; keep p in sacc
#pragma unroll
        for (int ni = 0; ni < 8; ni++) {
            int col = k0 + ni * 8 + tg * 2;
            float2 mv = *(const float2*)&mask[(size_t)b * Sq + col];
            float mx = mv.x * -1e9f, my = mv.y * -1e9f;
            float p0 = __expf(sacc[ni][0] * 0.125f + mx - mr0) * iz0;
            float p1 = __expf(sacc[ni][1] * 0.125f + my - mr0) * iz0;
            float p2 = __expf(sacc[ni][2] * 0.125f + mx - mr1) * iz1;
            float p3 = __expf(sacc[ni][3] * 0.125f + my - mr1) * iz1;
            int row = q0 + wid * 16 + g;
            *(float2*)&att[((size_t)bh * Sq + row) * Sq + col] = make_float2(p0, p1);
            *(float2*)&att[((size_t)bh * Sq + row + 8) * Sq + col] = make_float2(p2, p3);
            sacc[ni][0] = p0; sacc[ni][1] = p1; sacc[ni][2] = p2; sacc[ni][3] = p3;
        }

        // ctx += p @ V  (bf16x3; p A-fragments built from accumulators)
        {
            uint32_t brow = (lane & 7) + ((lane & 8) ? 8 : 0);
            uint32_t bcolb = (lane & 16) ? 16 : 0;
#pragma unroll
            for (int kt = 0; kt < 4; kt++) {
                int j = kt * 2;
                uint32_t ah[4], al[4];
                hilo2(sacc[j][0], sacc[j][1], ah[0], al[0]);
                hilo2(sacc[j][2], sacc[j][3], ah[1], al[1]);
                hilo2(sacc[j + 1][0], sacc[j + 1][1], ah[2], al[2]);
                hilo2(sacc[j + 1][2], sacc[j + 1][3], ah[3], al[3]);
#pragma unroll
                for (int np = 0; np < 4; np++) {
                    uint32_t bh4[4], bl4[4];
                    ldsm_x4_trans(bh4, sb + FA_VHIo + (kt * 16 + brow) * 144 + np * 32 + bcolb);
                    mma_bf16(cacc[np * 2 + 0], ah, bh4[0], bh4[1]);
                    mma_bf16(cacc[np * 2 + 1], ah, bh4[2], bh4[3]);
                    mma_bf16(cacc[np * 2 + 0], al, bh4[0], bh4[1]);
                    mma_bf16(cacc[np * 2 + 1], al, bh4[2], bh4[3]);
                    ldsm_x4_trans(bl4, sb + FA_VLOo + (kt * 16 + brow) * 144 + np * 32 + bcolb);
                    mma_bf16(cacc[np * 2 + 0], ah, bl4[0], bl4[1]);
                    mma_bf16(cacc[np * 2 + 1], ah, bl4[2], bl4[3]);
                }
            }
        }
        __syncthreads();
    }

    // Write ctx (16 rows x 64 cols per warp)
#pragma unroll
    for (int ni = 0; ni < 8; ni++) {
        int col = h * 64 + ni * 8 + tg * 2;
        int row = q0 + wid * 16 + g;
        *(float2*)&ctx[(size_t)(b * Sq + row) * DMq + col] =
            make_float2(cacc[ni][0], cacc[ni][1]);
        *(float2*)&ctx[(size_t)(b * Sq + row + 8) * DMq + col] =
            make_float2(cacc[ni][2], cacc[ni][3]);
    }
}

// ---------------------------------------------------------------------------
extern "C" void kernel_launch(void* const* d_in, const int* in_sizes, int n_in,
                              void* d_out, int out_size)
{
    const float* Q    = (const float*)d_in[0];
    const float* K    = (const float*)d_in[1];
    const float* V    = (const float*)d_in[2];
    const float* mask = (const float*)d_in[3];
    const float* Wq   = (const float*)d_in[4];
    const float* bq   = (const float*)d_in[5];
    const float* Wk   = (const float*)d_in[6];
    const float* bk   = (const float*)d_in[7];
    const float* Wv   = (const float*)d_in[8];
    const float* bv   = (const float*)d_in[9];
    const float* Wo   = (const float*)d_in[10];
    const float* bo   = (const float*)d_in[11];

    __nv_bfloat16 *qhi, *qlo, *khi, *klo, *vhi, *vlo;
    float *cp, *pm, *pz, *rm, *ri;
    cudaGetSymbolAddress((void**)&qhi, g_qhi);
    cudaGetSymbolAddress((void**)&qlo, g_qlo);
    cudaGetSymbolAddress((void**)&khi, g_khi);
    cudaGetSymbolAddress((void**)&klo, g_klo);
    cudaGetSymbolAddress((void**)&vhi, g_vhi);
    cudaGetSymbolAddress((void**)&vlo, g_vlo);
    cudaGetSymbolAddress((void**)&cp, g_ctx);
    cudaGetSymbolAddress((void**)&pm, g_pm);
    cudaGetSymbolAddress((void**)&pz, g_pz);
    cudaGetSymbolAddress((void**)&rm, g_rowm);
    cudaGetSymbolAddress((void**)&ri, g_rowinv);

    float* Y   = (float*)d_out;
    float* att = Y + Y_ELEMS;

    cudaFuncSetAttribute(stats_mma_kernel,
                         cudaFuncAttributeMaxDynamicSharedMemorySize, SC_SMEM_BYTES);
    cudaFuncSetAttribute(attn_fused_kernel,
                         cudaFuncAttributeMaxDynamicSharedMemorySize, FA_SMEM_BYTES);

    dim3 gproj(DMq / 128, BSq / 128);
    gemm_bias128_kernel<<<gproj, 256>>>(Q, Wq, bq, nullptr, qhi, qlo, BSq, DMq, DMq);
    gemm_bias128_kernel<<<gproj, 256>>>(K, Wk, bk, nullptr, khi, klo, BSq, DMq, DMq);
    gemm_bias128_kernel<<<gproj, 256>>>(V, Wv, bv, nullptr, vhi, vlo, BSq, DMq, DMq);

    dim3 gsc(Sq / 128, Sq / 128, Bq * Hq);
    stats_mma_kernel<<<gsc, 256, SC_SMEM_BYTES>>>(qhi, qlo, khi, klo, mask, pm, pz);

    softmax_reduce_kernel<<<NROWS / 256, 256>>>(pm, pz, rm, ri);

    dim3 gfa(Sq / 128, Bq * Hq);
    attn_fused_kernel<<<gfa, 256, FA_SMEM_BYTES>>>(qhi, qlo, khi, klo, vhi, vlo,
                                                   mask, rm, ri, att, cp);

    gemm_bias128_kernel<<<gproj, 256>>>(cp, Wo, bo, Y, nullptr, nullptr, BSq, DMq, DMq);
}

// round 6
// speedup vs baseline: 1.5145x; 1.5145x over previous
#include <cuda_runtime.h>
#include <cuda_bf16.h>
#include <cstdint>
#include <math.h>

#define Bq 4
#define Sq 2048
#define DMq 512
#define Hq 8
#define BSq (Bq * Sq)
#define Y_ELEMS ((size_t)Bq * Sq * DMq)
#define NROWS (Bq * Hq * Sq)
#define NTILES 16

// ---------------- Scratch (__device__ globals) ----------------
__device__ __nv_bfloat16 g_iqhi[Bq * Sq * DMq];   // input splits
__device__ __nv_bfloat16 g_iqlo[Bq * Sq * DMq];
__device__ __nv_bfloat16 g_ikhi[Bq * Sq * DMq];
__device__ __nv_bfloat16 g_iklo[Bq * Sq * DMq];
__device__ __nv_bfloat16 g_ivhi[Bq * Sq * DMq];
__device__ __nv_bfloat16 g_ivlo[Bq * Sq * DMq];
__device__ __nv_bfloat16 g_whi[4][DMq * DMq];     // Wq,Wk,Wv,Wo splits
__device__ __nv_bfloat16 g_wlo[4][DMq * DMq];
__device__ __nv_bfloat16 g_qhi[Bq * Sq * DMq];    // projection outputs
__device__ __nv_bfloat16 g_qlo[Bq * Sq * DMq];
__device__ __nv_bfloat16 g_khi[Bq * Sq * DMq];
__device__ __nv_bfloat16 g_klo[Bq * Sq * DMq];
__device__ __nv_bfloat16 g_vhi[Bq * Sq * DMq];
__device__ __nv_bfloat16 g_vlo[Bq * Sq * DMq];
__device__ __nv_bfloat16 g_ctxhi[Bq * Sq * DMq];
__device__ __nv_bfloat16 g_ctxlo[Bq * Sq * DMq];
__device__ float g_pm[(size_t)NROWS * NTILES];
__device__ float g_pz[(size_t)NROWS * NTILES];
__device__ float g_rowm[NROWS];
__device__ float g_rowinv[NROWS];

// ---------------- helpers ----------------
__device__ __forceinline__ uint32_t smem_u32(const void* p) {
    uint32_t a;
    asm("{ .reg .u64 t; cvta.to.shared.u64 t, %1; cvt.u32.u64 %0, t; }"
        : "=r"(a) : "l"(p));
    return a;
}

__device__ __forceinline__ void ldsm_x4(uint32_t* r, uint32_t addr) {
    asm volatile("ldmatrix.sync.aligned.m8n8.x4.shared.b16 {%0,%1,%2,%3}, [%4];"
                 : "=r"(r[0]), "=r"(r[1]), "=r"(r[2]), "=r"(r[3]) : "r"(addr));
}

__device__ __forceinline__ void ldsm_x4_trans(uint32_t* r, uint32_t addr) {
    asm volatile("ldmatrix.sync.aligned.m8n8.x4.trans.shared.b16 {%0,%1,%2,%3}, [%4];"
                 : "=r"(r[0]), "=r"(r[1]), "=r"(r[2]), "=r"(r[3]) : "r"(addr));
}

__device__ __forceinline__ void mma_bf16(float* d, const uint32_t* a,
                                         uint32_t b0, uint32_t b1) {
    asm volatile(
        "mma.sync.aligned.m16n8k16.row.col.f32.bf16.bf16.f32 "
        "{%0,%1,%2,%3}, {%4,%5,%6,%7}, {%8,%9}, {%0,%1,%2,%3};"
        : "+f"(d[0]), "+f"(d[1]), "+f"(d[2]), "+f"(d[3])
        : "r"(a[0]), "r"(a[1]), "r"(a[2]), "r"(a[3]), "r"(b0), "r"(b1));
}

__device__ __forceinline__ uint32_t pack_bf16(float x, float y) {
    __nv_bfloat162 t = __floats2bfloat162_rn(x, y);
    return *reinterpret_cast<uint32_t*>(&t);
}

__device__ __forceinline__ void hilo2(float x, float y, uint32_t& hi, uint32_t& lo) {
    __nv_bfloat16 hx = __float2bfloat16_rn(x), hy = __float2bfloat16_rn(y);
    __nv_bfloat162 hv;
    hv.x = hx; hv.y = hy;
    hi = *reinterpret_cast<uint32_t*>(&hv);
    lo = pack_bf16(x - __bfloat162float(hx), y - __bfloat162float(hy));
}

__device__ __forceinline__ void cp_async16(uint32_t dst, const void* src) {
    asm volatile("cp.async.cg.shared.global [%0], [%1], 16;" :: "r"(dst), "l"(src));
}
#define CP_COMMIT() asm volatile("cp.async.commit_group;" ::: "memory")
#define CP_WAIT1()  asm volatile("cp.async.wait_group 1;" ::: "memory")

// ---------------------------------------------------------------------------
// fp32 -> bf16 hi/lo split
// ---------------------------------------------------------------------------
__global__ __launch_bounds__(256) void split_kernel(
    const float* __restrict__ src, __nv_bfloat16* __restrict__ hi,
    __nv_bfloat16* __restrict__ lo, int n4)
{
    int i = blockIdx.x * 256 + threadIdx.x;
    if (i >= n4) return;
    float4 v = reinterpret_cast<const float4*>(src)[i];
    uint2 h, l;
    hilo2(v.x, v.y, h.x, l.x);
    hilo2(v.z, v.w, h.y, l.y);
    reinterpret_cast<uint2*>(hi)[i] = h;
    reinterpret_cast<uint2*>(lo)[i] = l;
}

// ---------------------------------------------------------------------------
// Projection GEMM via bf16x3 mma.sync: C[8192x512] = A @ W + bias
// A row-major hi/lo, W [K][N] row-major hi/lo (trans-ldsm).
// Tile 128x128, 256 threads (4x2 warps of 32x64).
// ---------------------------------------------------------------------------
#define PJ_AHIo 0
#define PJ_ALOo 18432
#define PJ_WHIo 36864
#define PJ_WLOo (36864 + 17408)
#define PJ_SMEM_BYTES (36864 + 2 * 17408)

__global__ __launch_bounds__(256, 2) void proj_mma_kernel(
    const __nv_bfloat16* __restrict__ Ahi, const __nv_bfloat16* __restrict__ Alo,
    const __nv_bfloat16* __restrict__ Whi, const __nv_bfloat16* __restrict__ Wlo,
    const float* __restrict__ bias,
    __nv_bfloat16* __restrict__ Ohi, __nv_bfloat16* __restrict__ Olo,
    float* __restrict__ Of)
{
    extern __shared__ char sm[];
    char* bp = sm;
    uint32_t sb = smem_u32(sm);
    const int N = DMq, Kd = DMq;

    int tid = threadIdx.x;
    int lane = tid & 31, wid = tid >> 5;
    int wq = wid >> 1, wn = wid & 1;
    int m0 = blockIdx.y * 128, n0 = blockIdx.x * 128;

    float acc[2][8][4] = {};

    const uint32_t Ao[3] = {PJ_AHIo, PJ_AHIo, PJ_ALOo};
    const uint32_t Wo[3] = {PJ_WHIo, PJ_WLOo, PJ_WHIo};

    for (int k0 = 0; k0 < Kd; k0 += 64) {
        // A chunk: 128 rows x 64 cols hi/lo
        for (int it = tid; it < 1024; it += 256) {
            int row = it >> 3, ch = it & 7;
            int so = row * 144 + ch * 16;
            size_t g = (size_t)(m0 + row) * Kd + k0 + ch * 8;
            *(uint4*)(bp + PJ_AHIo + so) = *(const uint4*)(Ahi + g);
            *(uint4*)(bp + PJ_ALOo + so) = *(const uint4*)(Alo + g);
        }
        // W chunk: 64 k-rows x 128 n-cols hi/lo (stride 272)
        for (int it = tid; it < 1024; it += 256) {
            int row = it >> 4, c8 = it & 15;
            int so = row * 272 + c8 * 16;
            size_t g = (size_t)(k0 + row) * N + n0 + c8 * 8;
            *(uint4*)(bp + PJ_WHIo + so) = *(const uint4*)(Whi + g);
            *(uint4*)(bp + PJ_WLOo + so) = *(const uint4*)(Wlo + g);
        }
        __syncthreads();

#pragma unroll
        for (int p = 0; p < 3; p++) {
            uint32_t abase = sb + Ao[p] + (wq * 32) * 144;
            uint32_t wbase = sb + Wo[p] + wn * 128;
            uint32_t arow = lane & 15;
            uint32_t acolb = (lane >> 4) * 16;
            uint32_t brow = (lane & 7) + ((lane & 8) ? 8 : 0);
            uint32_t bcolb = (lane & 16) ? 16 : 0;
#pragma unroll
            for (int kt = 0; kt < 4; kt++) {
                uint32_t a0[4], a1[4];
                ldsm_x4(a0, abase + arow * 144 + acolb + kt * 32);
                ldsm_x4(a1, abase + (16 + arow) * 144 + acolb + kt * 32);
#pragma unroll
                for (int np = 0; np < 4; np++) {
                    uint32_t bb[4];
                    ldsm_x4_trans(bb, wbase + (kt * 16 + brow) * 272 + np * 32 + bcolb);
                    mma_bf16(acc[0][np * 2 + 0], a0, bb[0], bb[1]);
                    mma_bf16(acc[0][np * 2 + 1], a0, bb[2], bb[3]);
                    mma_bf16(acc[1][np * 2 + 0], a1, bb[0], bb[1]);
                    mma_bf16(acc[1][np * 2 + 1], a1, bb[2], bb[3]);
                }
            }
        }
        __syncthreads();
    }

    int g = lane >> 2, tg = lane & 3;
#pragma unroll
    for (int ni = 0; ni < 8; ni++) {
        int col = n0 + wn * 64 + ni * 8 + tg * 2;
        float2 bv = *(const float2*)&bias[col];
#pragma unroll
        for (int mi = 0; mi < 2; mi++) {
#pragma unroll
            for (int half = 0; half < 2; half++) {
                int row = m0 + wq * 32 + mi * 16 + g + half * 8;
                float x = acc[mi][ni][half * 2 + 0] + bv.x;
                float y = acc[mi][ni][half * 2 + 1] + bv.y;
                size_t idx = (size_t)row * N + col;
                if (Of) *(float2*)&Of[idx] = make_float2(x, y);
                if (Ohi) {
                    uint32_t hv, lv;
                    hilo2(x, y, hv, lv);
                    *(uint32_t*)&Ohi[idx] = hv;
                    *(uint32_t*)&Olo[idx] = lv;
                }
            }
        }
    }
}

// ---------------------------------------------------------------------------
// Stats kernel (unchanged): per-tile softmax partials via bf16x3 MMA.
// ---------------------------------------------------------------------------
#define SC_TILE_BYTES (128 * 144)
#define SC_STATS_OFF (4 * SC_TILE_BYTES)
#define SC_SMEM_BYTES (4 * SC_TILE_BYTES + 2048)

__global__ __launch_bounds__(256, 2) void stats_mma_kernel(
    const __nv_bfloat16* __restrict__ qhi, const __nv_bfloat16* __restrict__ qlo,
    const __nv_bfloat16* __restrict__ khi, const __nv_bfloat16* __restrict__ klo,
    const float* __restrict__ mask,
    float* __restrict__ pm, float* __restrict__ pz)
{
    extern __shared__ char sm[];
    char* bp = sm;
    uint32_t sb = smem_u32(sm);
    const uint32_t QHIo = 0, QLOo = SC_TILE_BYTES, KHIo = 2 * SC_TILE_BYTES,
                   KLOo = 3 * SC_TILE_BYTES;
    float* sm_m = (float*)(bp + SC_STATS_OFF);
    float* sm_z = sm_m + 256;

    int tid = threadIdx.x;
    int lane = tid & 31, wid = tid >> 5;
    int wq = wid >> 1, wn = wid & 1;
    int bh = blockIdx.z, b = bh >> 3, h = bh & 7;
    int q0 = blockIdx.y * 128;
    int n0 = blockIdx.x * 128;

    for (int it = tid; it < 1024; it += 256) {
        int row = it >> 3, ch = it & 7;
        int so = row * 144 + ch * 16;
        size_t gq = ((size_t)(b * Sq + q0 + row)) * DMq + h * 64 + ch * 8;
        size_t gk = ((size_t)(b * Sq + n0 + row)) * DMq + h * 64 + ch * 8;
        *(uint4*)(bp + QHIo + so) = *(const uint4*)(qhi + gq);
        *(uint4*)(bp + QLOo + so) = *(const uint4*)(qlo + gq);
        *(uint4*)(bp + KHIo + so) = *(const uint4*)(khi + gk);
        *(uint4*)(bp + KLOo + so) = *(const uint4*)(klo + gk);
    }
    __syncthreads();

    float acc[2][8][4] = {};
    const uint32_t Aoff[3] = {QHIo, QHIo, QLOo};
    const uint32_t Boff[3] = {KHIo, KLOo, KHIo};

#pragma unroll
    for (int p = 0; p < 3; p++) {
        uint32_t abase = sb + Aoff[p] + (wq * 32) * 144;
        uint32_t bbase = sb + Boff[p] + (wn * 64) * 144;
        uint32_t arow = lane & 15;
        uint32_t acolb = (lane >> 4) * 16;
#pragma unroll
        for (int kt = 0; kt < 4; kt++) {
            uint32_t a0[4], a1[4];
            ldsm_x4(a0, abase + arow * 144 + acolb + kt * 32);
            ldsm_x4(a1, abase + (16 + arow) * 144 + acolb + kt * 32);
            uint32_t brow = (lane & 7) + ((lane & 16) ? 8 : 0);
            uint32_t bcolb = ((lane >> 3) & 1) * 16 + kt * 32;
#pragma unroll
            for (int np = 0; np < 4; np++) {
                uint32_t bb[4];
                ldsm_x4(bb, bbase + (brow + np * 16) * 144 + bcolb);
                mma_bf16(acc[0][np * 2 + 0], a0, bb[0], bb[1]);
                mma_bf16(acc[0][np * 2 + 1], a0, bb[2], bb[3]);
                mma_bf16(acc[1][np * 2 + 0], a1, bb[0], bb[1]);
                mma_bf16(acc[1][np * 2 + 1], a1, bb[2], bb[3]);
            }
        }
    }

    int g = lane >> 2, tg = lane & 3;
    float mrow[4] = {-1e30f, -1e30f, -1e30f, -1e30f};
#pragma unroll
    for (int ni = 0; ni < 8; ni++) {
        int col = n0 + wn * 64 + ni * 8 + tg * 2;
        float2 mv = *(const float2*)&mask[(size_t)b * Sq + col];
        float mx = mv.x * -1e9f, my = mv.y * -1e9f;
#pragma unroll
        for (int mi = 0; mi < 2; mi++) {
            float v0 = acc[mi][ni][0] * 0.125f + mx;
            float v1 = acc[mi][ni][1] * 0.125f + my;
            float v2 = acc[mi][ni][2] * 0.125f + mx;
            float v3 = acc[mi][ni][3] * 0.125f + my;
            mrow[mi * 2 + 0] = fmaxf(mrow[mi * 2 + 0], fmaxf(v0, v1));
            mrow[mi * 2 + 1] = fmaxf(mrow[mi * 2 + 1], fmaxf(v2, v3));
        }
    }
#pragma unroll
    for (int r = 0; r < 4; r++) {
        mrow[r] = fmaxf(mrow[r], __shfl_xor_sync(0xffffffffu, mrow[r], 1));
        mrow[r] = fmaxf(mrow[r], __shfl_xor_sync(0xffffffffu, mrow[r], 2));
    }
    float zrow[4] = {0.f, 0.f, 0.f, 0.f};
#pragma unroll
    for (int ni = 0; ni < 8; ni++) {
        int col = n0 + wn * 64 + ni * 8 + tg * 2;
        float2 mv = *(const float2*)&mask[(size_t)b * Sq + col];
        float mx = mv.x * -1e9f, my = mv.y * -1e9f;
#pragma unroll
        for (int mi = 0; mi < 2; mi++) {
            float v0 = acc[mi][ni][0] * 0.125f + mx;
            float v1 = acc[mi][ni][1] * 0.125f + my;
            float v2 = acc[mi][ni][2] * 0.125f + mx;
            float v3 = acc[mi][ni][3] * 0.125f + my;
            zrow[mi * 2 + 0] += __expf(v0 - mrow[mi * 2 + 0]) + __expf(v1 - mrow[mi * 2 + 0]);
            zrow[mi * 2 + 1] += __expf(v2 - mrow[mi * 2 + 1]) + __expf(v3 - mrow[mi * 2 + 1]);
        }
    }
#pragma unroll
    for (int r = 0; r < 4; r++) {
        zrow[r] += __shfl_xor_sync(0xffffffffu, zrow[r], 1);
        zrow[r] += __shfl_xor_sync(0xffffffffu, zrow[r], 2);
    }
    if (tg == 0) {
#pragma unroll
        for (int mi = 0; mi < 2; mi++) {
#pragma unroll
            for (int half = 0; half < 2; half++) {
                int rloc = wq * 32 + mi * 16 + g + half * 8;
                sm_m[wn * 128 + rloc] = mrow[mi * 2 + half];
                sm_z[wn * 128 + rloc] = zrow[mi * 2 + half];
            }
        }
    }
    __syncthreads();
    if (tid < 128) {
        float m0 = sm_m[tid], m1 = sm_m[128 + tid];
        float mm = fmaxf(m0, m1);
        float zz = sm_z[tid] * __expf(m0 - mm) + sm_z[128 + tid] * __expf(m1 - mm);
        size_t pidx = ((size_t)bh * Sq + q0 + tid) * NTILES + blockIdx.x;
        pm[pidx] = mm;
        pz[pidx] = zz;
    }
}

// ---------------------------------------------------------------------------
__global__ __launch_bounds__(256) void softmax_reduce_kernel(
    const float* __restrict__ pm, const float* __restrict__ pz,
    float* __restrict__ rowm, float* __restrict__ rowinv)
{
    int idx = blockIdx.x * 256 + threadIdx.x;
    if (idx >= NROWS) return;
    const float* pmp = pm + (size_t)idx * NTILES;
    const float* pzp = pz + (size_t)idx * NTILES;
    float m = -1e30f;
#pragma unroll
    for (int t = 0; t < NTILES; t++) m = fmaxf(m, pmp[t]);
    float z = 0.f;
#pragma unroll
    for (int t = 0; t < NTILES; t++) z += pzp[t] * __expf(pmp[t] - m);
    rowm[idx] = m;
    rowinv[idx] = 1.0f / z;
}

// ---------------------------------------------------------------------------
// Fused attention v2: cp.async double-buffered K/V; recompute S, p, write att,
// ctx += p@V; ctx epilogue writes hi/lo bf16 for the out-projection.
// ---------------------------------------------------------------------------
#define FA_QHIo 0
#define FA_QLOo 18432
#define FA_STG0 36864
#define FA_STGSZ 36864
#define FA_KHIo 0
#define FA_KLOo 9216
#define FA_VHIo 18432
#define FA_VLOo 27648
#define FA_STATo (FA_STG0 + 2 * FA_STGSZ)
#define FA_SMEM_BYTES (FA_STATo + 1024)

__global__ __launch_bounds__(256, 2) void attn_fused_kernel(
    const __nv_bfloat16* __restrict__ qhi, const __nv_bfloat16* __restrict__ qlo,
    const __nv_bfloat16* __restrict__ khi, const __nv_bfloat16* __restrict__ klo,
    const __nv_bfloat16* __restrict__ vhi, const __nv_bfloat16* __restrict__ vlo,
    const float* __restrict__ mask,
    const float* __restrict__ rowm, const float* __restrict__ rowinv,
    float* __restrict__ att,
    __nv_bfloat16* __restrict__ ctxhi, __nv_bfloat16* __restrict__ ctxlo)
{
    extern __shared__ char sm[];
    char* bp = sm;
    uint32_t sb = smem_u32(sm);
    float* sm_m = (float*)(bp + FA_STATo);
    float* sm_iz = sm_m + 128;

    int tid = threadIdx.x;
    int lane = tid & 31, wid = tid >> 5;
    int g = lane >> 2, tg = lane & 3;
    int bh = blockIdx.y, b = bh >> 3, h = bh & 7;
    int q0 = blockIdx.x * 128;

    size_t kvbase = (size_t)b * Sq * DMq + h * 64;

    // Q tile + row stats (plain loads, once)
    for (int it = tid; it < 1024; it += 256) {
        int row = it >> 3, ch = it & 7;
        int so = row * 144 + ch * 16;
        size_t gq = ((size_t)(b * Sq + q0 + row)) * DMq + h * 64 + ch * 8;
        *(uint4*)(bp + FA_QHIo + so) = *(const uint4*)(qhi + gq);
        *(uint4*)(bp + FA_QLOo + so) = *(const uint4*)(qlo + gq);
    }
    if (tid < 128) {
        sm_m[tid] = rowm[(size_t)bh * Sq + q0 + tid];
        sm_iz[tid] = rowinv[(size_t)bh * Sq + q0 + tid];
    }

    // K/V chunk prefetch via cp.async (stage: Khi,Klo,Vhi,Vlo @ 64x144 each)
    const __nv_bfloat16* mats[4] = {khi, klo, vhi, vlo};
#define LOAD_STAGE(sidx, kk0) do { \
    uint32_t stb = sb + FA_STG0 + (sidx) * FA_STGSZ; \
    _Pragma("unroll") \
    for (int mat = 0; mat < 4; mat++) { \
        const __nv_bfloat16* srcm = mats[mat]; \
        _Pragma("unroll") \
        for (int i2 = 0; i2 < 2; i2++) { \
            int i = tid + i2 * 256; \
            int row = i >> 3, ch = i & 7; \
            cp_async16(stb + mat * 9216 + row * 144 + ch * 16, \
                       srcm + kvbase + (size_t)((kk0) + row) * DMq + ch * 8); \
        } \
    } \
} while (0)

    LOAD_STAGE(0, 0);
    CP_COMMIT();
    LOAD_STAGE(1, 64);
    CP_COMMIT();

    __syncthreads();
    float mr0 = sm_m[wid * 16 + g], iz0 = sm_iz[wid * 16 + g];
    float mr1 = sm_m[wid * 16 + g + 8], iz1 = sm_iz[wid * 16 + g + 8];

    float cacc[8][4] = {};
    const uint32_t Ao[3] = {FA_QHIo, FA_QHIo, FA_QLOo};

    for (int c = 0; c < 32; c++) {
        CP_WAIT1();
        __syncthreads();
        uint32_t stg = FA_STG0 + (uint32_t)(c & 1) * FA_STGSZ;
        int k0 = c * 64;

        // Scores: warp tile 16 rows x 64 cols, bf16x3
        float sacc[8][4] = {};
        const uint32_t Bo[3] = {stg + FA_KHIo, stg + FA_KLOo, stg + FA_KHIo};
#pragma unroll
        for (int p = 0; p < 3; p++) {
            uint32_t abase = sb + Ao[p] + (wid * 16) * 144;
            uint32_t bbase = sb + Bo[p];
            uint32_t arow = lane & 15;
            uint32_t acolb = (lane >> 4) * 16;
            uint32_t brow = (lane & 7) + ((lane & 16) ? 8 : 0);
            uint32_t bcolb = ((lane >> 3) & 1) * 16;
#pragma unroll
            for (int kt = 0; kt < 4; kt++) {
                uint32_t a0[4];
                ldsm_x4(a0, abase + arow * 144 + acolb + kt * 32);
#pragma unroll
                for (int np = 0; np < 4; np++) {
                    uint32_t bb[4];
                    ldsm_x4(bb, bbase + (brow + np * 16) * 144 + bcolb + kt * 32);
                    mma_bf16(sacc[np * 2 + 0], a0, bb[0], bb[1]);
                    mma_bf16(sacc[np * 2 + 1], a0, bb[2], bb[3]);
                }
            }
        }

        // p = exp(scale*s + mask - m) * invZ; store normalized att
#pragma unroll
        for (int ni = 0; ni < 8; ni++) {
            int col = k0 + ni * 8 + tg * 2;
            float2 mv = *(const float2*)&mask[(size_t)b * Sq + col];
            float mx = mv.x * -1e9f, my = mv.y * -1e9f;
            float p0 = __expf(sacc[ni][0] * 0.125f + mx - mr0) * iz0;
            float p1 = __expf(sacc[ni][1] * 0.125f + my - mr0) * iz0;
            float p2 = __expf(sacc[ni][2] * 0.125f + mx - mr1) * iz1;
            float p3 = __expf(sacc[ni][3] * 0.125f + my - mr1) * iz1;
            int row = q0 + wid * 16 + g;
            *(float2*)&att[((size_t)bh * Sq + row) * Sq + col] = make_float2(p0, p1);
            *(float2*)&att[((size_t)bh * Sq + row + 8) * Sq + col] = make_float2(p2, p3);
            sacc[ni][0] = p0; sacc[ni][1] = p1; sacc[ni][2] = p2; sacc[ni][3] = p3;
        }

        // ctx += p @ V
        {
            uint32_t brow = (lane & 7) + ((lane & 8) ? 8 : 0);
            uint32_t bcolb = (lane & 16) ? 16 : 0;
#pragma unroll
            for (int kt = 0; kt < 4; kt++) {
                int j = kt * 2;
                uint32_t ah[4], al[4];
                hilo2(sacc[j][0], sacc[j][1], ah[0], al[0]);
                hilo2(sacc[j][2], sacc[j][3], ah[1], al[1]);
                hilo2(sacc[j + 1][0], sacc[j + 1][1], ah[2], al[2]);
                hilo2(sacc[j + 1][2], sacc[j + 1][3], ah[3], al[3]);
#pragma unroll
                for (int np = 0; np < 4; np++) {
                    uint32_t bh4[4], bl4[4];
                    ldsm_x4_trans(bh4, sb + stg + FA_VHIo + (kt * 16 + brow) * 144 + np * 32 + bcolb);
                    mma_bf16(cacc[np * 2 + 0], ah, bh4[0], bh4[1]);
                    mma_bf16(cacc[np * 2 + 1], ah, bh4[2], bh4[3]);
                    mma_bf16(cacc[np * 2 + 0], al, bh4[0], bh4[1]);
                    mma_bf16(cacc[np * 2 + 1], al, bh4[2], bh4[3]);
                    ldsm_x4_trans(bl4, sb + stg + FA_VLOo + (kt * 16 + brow) * 144 + np * 32 + bcolb);
                    mma_bf16(cacc[np * 2 + 0], ah, bl4[0], bl4[1]);
                    mma_bf16(cacc[np * 2 + 1], ah, bl4[2], bl4[3]);
                }
            }
        }
        __syncthreads();
        if (c + 2 < 32) LOAD_STAGE(c & 1, (c + 2) * 64);
        CP_COMMIT();
    }

    // ctx epilogue -> hi/lo bf16
#pragma unroll
    for (int ni = 0; ni < 8; ni++) {
        int col = h * 64 + ni * 8 + tg * 2;
        int row = q0 + wid * 16 + g;
        uint32_t hv, lv;
        size_t i0 = (size_t)(b * Sq + row) * DMq + col;
        hilo2(cacc[ni][0], cacc[ni][1], hv, lv);
        *(uint32_t*)&ctxhi[i0] = hv;
        *(uint32_t*)&ctxlo[i0] = lv;
        size_t i1 = (size_t)(b * Sq + row + 8) * DMq + col;
        hilo2(cacc[ni][2], cacc[ni][3], hv, lv);
        *(uint32_t*)&ctxhi[i1] = hv;
        *(uint32_t*)&ctxlo[i1] = lv;
    }
}

// ---------------------------------------------------------------------------
extern "C" void kernel_launch(void* const* d_in, const int* in_sizes, int n_in,
                              void* d_out, int out_size)
{
    const float* Q    = (const float*)d_in[0];
    const float* K    = (const float*)d_in[1];
    const float* V    = (const float*)d_in[2];
    const float* mask = (const float*)d_in[3];
    const float* Wq   = (const float*)d_in[4];
    const float* bq   = (const float*)d_in[5];
    const float* Wk   = (const float*)d_in[6];
    const float* bk   = (const float*)d_in[7];
    const float* Wv   = (const float*)d_in[8];
    const float* bv   = (const float*)d_in[9];
    const float* Wo   = (const float*)d_in[10];
    const float* bo   = (const float*)d_in[11];

    __nv_bfloat16 *iqhi, *iqlo, *ikhi, *iklo, *ivhi, *ivlo;
    __nv_bfloat16 *whi, *wlo;
    __nv_bfloat16 *qhi, *qlo, *khi, *klo, *vhi, *vlo, *cthi, *ctlo;
    float *pm, *pz, *rm, *ri;
    cudaGetSymbolAddress((void**)&iqhi, g_iqhi);
    cudaGetSymbolAddress((void**)&iqlo, g_iqlo);
    cudaGetSymbolAddress((void**)&ikhi, g_ikhi);
    cudaGetSymbolAddress((void**)&iklo, g_iklo);
    cudaGetSymbolAddress((void**)&ivhi, g_ivhi);
    cudaGetSymbolAddress((void**)&ivlo, g_ivlo);
    cudaGetSymbolAddress((void**)&whi, g_whi);
    cudaGetSymbolAddress((void**)&wlo, g_wlo);
    cudaGetSymbolAddress((void**)&qhi, g_qhi);
    cudaGetSymbolAddress((void**)&qlo, g_qlo);
    cudaGetSymbolAddress((void**)&khi, g_khi);
    cudaGetSymbolAddress((void**)&klo, g_klo);
    cudaGetSymbolAddress((void**)&vhi, g_vhi);
    cudaGetSymbolAddress((void**)&vlo, g_vlo);
    cudaGetSymbolAddress((void**)&cthi, g_ctxhi);
    cudaGetSymbolAddress((void**)&ctlo, g_ctxlo);
    cudaGetSymbolAddress((void**)&pm, g_pm);
    cudaGetSymbolAddress((void**)&pz, g_pz);
    cudaGetSymbolAddress((void**)&rm, g_rowm);
    cudaGetSymbolAddress((void**)&ri, g_rowinv);

    float* Y   = (float*)d_out;
    float* att = Y + Y_ELEMS;

    cudaFuncSetAttribute(proj_mma_kernel,
                         cudaFuncAttributeMaxDynamicSharedMemorySize, PJ_SMEM_BYTES);
    cudaFuncSetAttribute(stats_mma_kernel,
                         cudaFuncAttributeMaxDynamicSharedMemorySize, SC_SMEM_BYTES);
    cudaFuncSetAttribute(attn_fused_kernel,
                         cudaFuncAttributeMaxDynamicSharedMemorySize, FA_SMEM_BYTES);

    const int NIN4 = (Bq * Sq * DMq) / 4;     // 1,048,576
    const int NW4  = (DMq * DMq) / 4;         // 65,536
    split_kernel<<<(NIN4 + 255) / 256, 256>>>(Q, iqhi, iqlo, NIN4);
    split_kernel<<<(NIN4 + 255) / 256, 256>>>(K, ikhi, iklo, NIN4);
    split_kernel<<<(NIN4 + 255) / 256, 256>>>(V, ivhi, ivlo, NIN4);
    split_kernel<<<(NW4 + 255) / 256, 256>>>(Wq, whi + 0 * DMq * DMq, wlo + 0 * DMq * DMq, NW4);
    split_kernel<<<(NW4 + 255) / 256, 256>>>(Wk, whi + 1 * DMq * DMq, wlo + 1 * DMq * DMq, NW4);
    split_kernel<<<(NW4 + 255) / 256, 256>>>(Wv, whi + 2 * DMq * DMq, wlo + 2 * DMq * DMq, NW4);
    split_kernel<<<(NW4 + 255) / 256, 256>>>(Wo, whi + 3 * DMq * DMq, wlo + 3 * DMq * DMq, NW4);

    dim3 gproj(DMq / 128, BSq / 128);   // (4, 64)
    proj_mma_kernel<<<gproj, 256, PJ_SMEM_BYTES>>>(
        iqhi, iqlo, whi + 0 * DMq * DMq, wlo + 0 * DMq * DMq, bq, qhi, qlo, nullptr);
    proj_mma_kernel<<<gproj, 256, PJ_SMEM_BYTES>>>(
        ikhi, iklo, whi + 1 * DMq * DMq, wlo + 1 * DMq * DMq, bk, khi, klo, nullptr);
    proj_mma_kernel<<<gproj, 256, PJ_SMEM_BYTES>>>(
        ivhi, ivlo, whi + 2 * DMq * DMq, wlo + 2 * DMq * DMq, bv, vhi, vlo, nullptr);

    dim3 gsc(Sq / 128, Sq / 128, Bq * Hq);
    stats_mma_kernel<<<gsc, 256, SC_SMEM_BYTES>>>(qhi, qlo, khi, klo, mask, pm, pz);

    softmax_reduce_kernel<<<NROWS / 256, 256>>>(pm, pz, rm, ri);

    dim3 gfa(Sq / 128, Bq * Hq);
    attn_fused_kernel<<<gfa, 256, FA_SMEM_BYTES>>>(qhi, qlo, khi, klo, vhi, vlo,
                                                   mask, rm, ri, att, cthi, ctlo);

    proj_mma_kernel<<<gproj, 256, PJ_SMEM_BYTES>>>(
        cthi, ctlo, whi + 3 * DMq * DMq, wlo + 3 * DMq * DMq, bo, nullptr, nullptr, Y);
}